// round 10
// baseline (speedup 1.0000x reference)
#include <cuda_runtime.h>
#include <cuda_bf16.h>

#define T_STEPS 1000
#define BETA_1 1e-4
#define BETA_T 0.02

// ---- compile-time table: (sqrt(alpha_bar[t]), sqrt(1-alpha_bar[t])) ----
// Depends only on compile-time constants; baked into __constant__ memory so
// the graph has a single kernel node and zero table-init cost at runtime.

struct ScaleTable {
    float2 v[T_STEPS];
};

constexpr double csqrt(double x) {
    double g = x > 1.0 ? x : 1.0;
    for (int i = 0; i < 60; ++i) g = 0.5 * (g + x / g);
    return g;
}

constexpr ScaleTable make_table() {
    ScaleTable tbl{};
    const double slope = (BETA_T - BETA_1) / (double)(T_STEPS - 1);
    double ab = 1.0;
    for (int i = 0; i < T_STEPS; ++i) {
        double beta = BETA_1 + slope * (double)i;
        ab *= (1.0 - beta);
        tbl.v[i].x = (float)csqrt(ab);
        tbl.v[i].y = (float)csqrt(1.0 - ab);
    }
    return tbl;
}

__constant__ ScaleTable g_scales = make_table();

// ---- mix kernel: 1 float4 per thread, 3 linear DRAM streams, streaming hints ----
// HBM-roofline-bound: 616 MB irreducible traffic @ ~6.8 TB/s achieved => ~88-90 us.
// total4 = B * 196 (784 floats per image = 196 float4).
// BLK=1024: quarters the original CTA count (12544). CTA-count reduction is the
// one axis that measurably improved timed duration (R7: 512 -> -1.5us).

#define BLK 1024

__global__ void __launch_bounds__(BLK) ddpm_mix_kernel(
    const float4* __restrict__ images,
    const float4* __restrict__ e,
    const int* __restrict__ t,
    float4* __restrict__ out,
    int total4)
{
    const int idx = blockIdx.x * BLK + threadIdx.x;
    if (idx >= total4) return;

    // Front-batch both 16B loads (evict-first: data is touched exactly once)
    float4 im = __ldcs(&images[idx]);
    float4 ee = __ldcs(&e[idx]);

    const unsigned b = (unsigned)idx / 196u;       // magic-mul division
    const int ti = __ldg(&t[b]);                   // alpha_bar index = t (t_s-1)
    const float2 sc = g_scales.v[ti];

    float4 o;
    o.x = fmaf(sc.x, im.x, sc.y * ee.x);
    o.y = fmaf(sc.x, im.y, sc.y * ee.y);
    o.z = fmaf(sc.x, im.z, sc.y * ee.z);
    o.w = fmaf(sc.x, im.w, sc.y * ee.w);
    __stcs(&out[idx], o);
}

extern "C" void kernel_launch(void* const* d_in, const int* in_sizes, int n_in,
                              void* d_out, int out_size) {
    const float4* images = (const float4*)d_in[0];
    const float4* e      = (const float4*)d_in[1];
    const int*    t      = (const int*)d_in[2];
    float4* out          = (float4*)d_out;

    const int B = in_sizes[2];
    const int total4 = B * 196;
    const int grid = (total4 + BLK - 1) / BLK;

    ddpm_mix_kernel<<<grid, BLK>>>(images, e, t, out, total4);
}

// round 12
// speedup vs baseline: 1.0089x; 1.0089x over previous
#include <cuda_runtime.h>
#include <cuda_bf16.h>

#define T_STEPS 1000
#define BETA_1 1e-4
#define BETA_T 0.02

// ---- compile-time table: (sqrt(alpha_bar[t]), sqrt(1-alpha_bar[t])) ----
// Depends only on compile-time constants; baked into __constant__ memory so
// the graph has a single kernel node and zero table-init cost at runtime.

struct ScaleTable {
    float2 v[T_STEPS];
};

constexpr double csqrt(double x) {
    double g = x > 1.0 ? x : 1.0;
    for (int i = 0; i < 60; ++i) g = 0.5 * (g + x / g);
    return g;
}

constexpr ScaleTable make_table() {
    ScaleTable tbl{};
    const double slope = (BETA_T - BETA_1) / (double)(T_STEPS - 1);
    double ab = 1.0;
    for (int i = 0; i < T_STEPS; ++i) {
        double beta = BETA_1 + slope * (double)i;
        ab *= (1.0 - beta);
        tbl.v[i].x = (float)csqrt(ab);
        tbl.v[i].y = (float)csqrt(1.0 - ab);
    }
    return tbl;
}

__constant__ ScaleTable g_scales = make_table();

// ---- mix kernel: 1 float4 per thread, 3 linear DRAM streams, streaming hints ----
// HBM-roofline-bound: 616 MB irreducible traffic @ ~6.8 TB/s achieved => ~88 us.
// total4 = B * 196 (784 floats per image = 196 float4).
// BLK=512 is the measured sweet spot (R7: 88.6us; 1024 regressed, 256 slower).
// __launch_bounds__(512, 4): force 4 resident CTAs/SM (2048 thr = 100% occ;
// ncu showed only 3 resident at default), raising chip-wide outstanding loads.

#define BLK 512

__global__ void __launch_bounds__(BLK, 4) ddpm_mix_kernel(
    const float4* __restrict__ images,
    const float4* __restrict__ e,
    const int* __restrict__ t,
    float4* __restrict__ out,
    int total4)
{
    const int idx = blockIdx.x * BLK + threadIdx.x;
    if (idx >= total4) return;

    // Front-batch both 16B loads (evict-first: data is touched exactly once)
    float4 im = __ldcs(&images[idx]);
    float4 ee = __ldcs(&e[idx]);

    const unsigned b = (unsigned)idx / 196u;       // magic-mul division
    const int ti = __ldg(&t[b]);                   // alpha_bar index = t (t_s-1)
    const float2 sc = g_scales.v[ti];

    float4 o;
    o.x = fmaf(sc.x, im.x, sc.y * ee.x);
    o.y = fmaf(sc.x, im.y, sc.y * ee.y);
    o.z = fmaf(sc.x, im.z, sc.y * ee.z);
    o.w = fmaf(sc.x, im.w, sc.y * ee.w);
    __stcs(&out[idx], o);
}

extern "C" void kernel_launch(void* const* d_in, const int* in_sizes, int n_in,
                              void* d_out, int out_size) {
    const float4* images = (const float4*)d_in[0];
    const float4* e      = (const float4*)d_in[1];
    const int*    t      = (const int*)d_in[2];
    float4* out          = (float4*)d_out;

    const int B = in_sizes[2];
    const int total4 = B * 196;
    const int grid = (total4 + BLK - 1) / BLK;

    ddpm_mix_kernel<<<grid, BLK>>>(images, e, t, out, total4);
}